// round 5
// baseline (speedup 1.0000x reference)
#include <cuda_runtime.h>
#include <cstdint>

// Problem dims
#define G1 512
#define E_EDGES 16384
#define S1 8192
#define S2 8192
#define BT 128            // batch rows per CTA
#define PAD 20            // floats per staged x row (16 data + 4 pad, 16B-aligned, conflict-free)

typedef unsigned long long ull;

// -------- device scratch --------
__device__ int g_offsets[G1 + 1];
__device__ int g_edge_list[E_EDGES];   // packed: (t1 << 16) | e

// -------- fused precompute: histogram + scan + scatter, one CTA --------
__global__ __launch_bounds__(1024) void bucket_kernel(const int* __restrict__ ei) {
    __shared__ int cnt[G1];
    __shared__ int scn[G1];
    __shared__ int cur[G1];
    const int t = threadIdx.x;
    if (t < G1) cnt[t] = 0;
    __syncthreads();
    for (int e = t; e < E_EDGES; e += 1024) atomicAdd(&cnt[ei[e]], 1);
    __syncthreads();
    if (t < G1) scn[t] = cnt[t];
    __syncthreads();
    #pragma unroll
    for (int d = 1; d < G1; d <<= 1) {
        int v = 0;
        if (t < G1 && t >= d) v = scn[t - d];
        __syncthreads();
        if (t < G1) scn[t] += v;
        __syncthreads();
    }
    if (t < G1) {
        g_offsets[t + 1] = scn[t];
        if (t == 0) g_offsets[0] = 0;
        cur[t] = scn[t] - cnt[t];
    }
    __syncthreads();
    for (int e = t; e < E_EDGES; e += 1024) {
        int t0 = ei[e];
        int t1 = ei[E_EDGES + e];
        int pos = atomicAdd(&cur[t0], 1);
        g_edge_list[pos] = (t1 << 16) | e;
    }
}

// packed fp32x2 FMA: d.lo += a.lo*b.lo ; d.hi += a.hi*b.hi
__device__ __forceinline__ void fma2(ull& d, ull a, ull b) {
    asm("fma.rn.f32x2 %0, %1, %2, %0;" : "+l"(d) : "l"(a), "l"(b));
}
__device__ __forceinline__ ull dupf(float f) {
    ull r;
    asm("mov.b64 %0, {%1, %1};" : "=l"(r) : "f"(f));
    return r;
}
__device__ __forceinline__ void cp16(uint32_t smem_dst, const void* gptr) {
    asm volatile("cp.async.cg.shared.global [%0], [%1], 16;" :: "r"(smem_dst), "l"(gptr));
}
__device__ __forceinline__ void cp_commit() {
    asm volatile("cp.async.commit_group;");
}
__device__ __forceinline__ void cp_wait1() {
    asm volatile("cp.async.wait_group 1;");
}

union F2U  { ull u; float2 f; };
union V4U  { float4 f; ull u[2]; };

// -------- main SpMM kernel --------
// grid: (512 t0, 2 batch halves), 128 threads. Thread owns batch row bbase+tid,
// all 16 output columns of this t0-block (8 fma2 accumulator pairs).
__global__ __launch_bounds__(128) void spmm_kernel(
    const float* __restrict__ x,
    const float* __restrict__ values,
    const float* __restrict__ bias,
    float* __restrict__ out)
{
    __shared__ __align__(16) float xs[2][BT][PAD];    // 20 KB: double-buffered x tile
    __shared__ __align__(16) float vs[2][256];        //  2 KB: double-buffered V block

    const int tid   = threadIdx.x;
    const int t0    = blockIdx.x;
    const int bbase = blockIdx.y * BT;

    // fixed cp.async destinations for this thread
    uint32_t xdst[2][4];
    #pragma unroll
    for (int s = 0; s < 2; s++)
        #pragma unroll
        for (int q = 0; q < 4; q++) {
            const int lin = tid + (q << 7);
            xdst[s][q] = (uint32_t)__cvta_generic_to_shared(&xs[s][lin >> 2][(lin & 3) << 2]);
        }
    uint32_t vdst[2];
    vdst[0] = (uint32_t)__cvta_generic_to_shared(&vs[0][tid << 2]);
    vdst[1] = (uint32_t)__cvta_generic_to_shared(&vs[1][tid << 2]);

    ull acc[8];
    #pragma unroll
    for (int jp = 0; jp < 8; jp++) acc[jp] = 0ull;

    // preload bias
    float bias_r[16];
    {
        const float4* bg4 = reinterpret_cast<const float4*>(bias + t0 * 16);
        #pragma unroll
        for (int m = 0; m < 4; m++) {
            float4 b4 = __ldg(&bg4[m]);
            bias_r[4 * m + 0] = b4.x; bias_r[4 * m + 1] = b4.y;
            bias_r[4 * m + 2] = b4.z; bias_r[4 * m + 3] = b4.w;
        }
    }

    const int beg = g_offsets[t0];
    const int end = g_offsets[t0 + 1];

    if (beg < end) {
        // ---- prologue: issue edge `beg` into buffer 0 ----
        {
            const int packed = g_edge_list[beg];
            const int e  = packed & 0xFFFF;
            const int t1 = packed >> 16;
            const float* xg = x + (size_t)bbase * S1 + t1 * 16;
            #pragma unroll
            for (int q = 0; q < 4; q++) {
                const int lin = tid + (q << 7);
                cp16(xdst[0][q], xg + (size_t)(lin >> 2) * S1 + ((lin & 3) << 2));
            }
            if (tid < 64)
                cp16(vdst[0], values + ((size_t)e << 8) + (tid << 2));
            cp_commit();
        }

        for (int k = beg; k < end; k++) {
            const int c = (k - beg) & 1;

            __syncthreads();   // (A) compute on buffer c^1 done -> free to refill

            if (k + 1 < end) {
                const int packed = g_edge_list[k + 1];
                const int e  = packed & 0xFFFF;
                const int t1 = packed >> 16;
                const float* xg = x + (size_t)bbase * S1 + t1 * 16;
                #pragma unroll
                for (int q = 0; q < 4; q++) {
                    const int lin = tid + (q << 7);
                    cp16(xdst[c ^ 1][q], xg + (size_t)(lin >> 2) * S1 + ((lin & 3) << 2));
                }
                if (tid < 64)
                    cp16(vdst[c ^ 1], values + ((size_t)e << 8) + (tid << 2));
            }
            cp_commit();       // commit even if empty (group counting stays aligned)
            cp_wait1();        // edge k's group complete

            __syncthreads();   // (B) edge k's data visible

            // ---- compute on buffer c: own row (tid) x all 16 columns ----
            #pragma unroll
            for (int i4 = 0; i4 < 4; i4++) {
                const float4 x0 = *reinterpret_cast<const float4*>(&xs[c][tid][i4 << 2]);
                const float xf[4] = {x0.x, x0.y, x0.z, x0.w};
                #pragma unroll
                for (int ii = 0; ii < 4; ii++) {
                    const int i = (i4 << 2) + ii;
                    const ull a0 = dupf(xf[ii]);
                    V4U va, vb, vc2, vd;
                    va.f  = *reinterpret_cast<const float4*>(&vs[c][(i << 4) +  0]);
                    vb.f  = *reinterpret_cast<const float4*>(&vs[c][(i << 4) +  4]);
                    vc2.f = *reinterpret_cast<const float4*>(&vs[c][(i << 4) +  8]);
                    vd.f  = *reinterpret_cast<const float4*>(&vs[c][(i << 4) + 12]);
                    fma2(acc[0], a0, va.u[0]);
                    fma2(acc[1], a0, va.u[1]);
                    fma2(acc[2], a0, vb.u[0]);
                    fma2(acc[3], a0, vb.u[1]);
                    fma2(acc[4], a0, vc2.u[0]);
                    fma2(acc[5], a0, vc2.u[1]);
                    fma2(acc[6], a0, vd.u[0]);
                    fma2(acc[7], a0, vd.u[1]);
                }
            }
        }
    }

    // ---- epilogue: bias + one coalesced 64B row store ----
    {
        float o[16];
        #pragma unroll
        for (int jp = 0; jp < 8; jp++) {
            F2U u; u.u = acc[jp];
            o[2 * jp + 0] = u.f.x + bias_r[2 * jp + 0];
            o[2 * jp + 1] = u.f.y + bias_r[2 * jp + 1];
        }
        float* op = out + (size_t)(bbase + tid) * S2 + t0 * 16;
        #pragma unroll
        for (int m = 0; m < 4; m++) {
            *reinterpret_cast<float4*>(op + 4 * m) =
                make_float4(o[4 * m], o[4 * m + 1], o[4 * m + 2], o[4 * m + 3]);
        }
    }
}

// -------- launch --------
extern "C" void kernel_launch(void* const* d_in, const int* in_sizes, int n_in,
                              void* d_out, int out_size) {
    const float* x      = (const float*)d_in[0];   // (256, 8192)
    const float* values = (const float*)d_in[1];   // (4194304,)
    const float* bias   = (const float*)d_in[2];   // (8192,)
    const int*   eidx   = (const int*)d_in[3];     // (2, 16384)
    float* out = (float*)d_out;                    // (256, 8192)

    bucket_kernel<<<1, 1024>>>(eidx);
    dim3 grid(G1, 256 / BT);
    spmm_kernel<<<grid, 128>>>(x, values, bias, out);
}

// round 7
// speedup vs baseline: 1.1138x; 1.1138x over previous
#include <cuda_runtime.h>
#include <cstdint>

// Problem dims
#define G1 512
#define E_EDGES 16384
#define S1 8192
#define S2 8192
#define BT 128

typedef unsigned long long ull;

// -------- device scratch --------
__device__ int g_offsets[G1 + 1];
__device__ int g_edge_list[E_EDGES];        // packed: (t1 << 16) | e
__device__ float g_xperm[256 * S1];         // 8MB: x, tf32-rounded, K-cols permuted per 16-block

// -------- fused precompute: histogram + scan + scatter, one CTA --------
__global__ __launch_bounds__(1024) void bucket_kernel(const int* __restrict__ ei) {
    __shared__ int cnt[G1];
    __shared__ int scn[G1];
    __shared__ int cur[G1];
    const int t = threadIdx.x;
    if (t < G1) cnt[t] = 0;
    __syncthreads();
    for (int e = t; e < E_EDGES; e += 1024) atomicAdd(&cnt[ei[e]], 1);
    __syncthreads();
    if (t < G1) scn[t] = cnt[t];
    __syncthreads();
    #pragma unroll
    for (int d = 1; d < G1; d <<= 1) {
        int v = 0;
        if (t < G1 && t >= d) v = scn[t - d];
        __syncthreads();
        if (t < G1) scn[t] += v;
        __syncthreads();
    }
    if (t < G1) {
        g_offsets[t + 1] = scn[t];
        if (t == 0) g_offsets[0] = 0;
        cur[t] = scn[t] - cnt[t];
    }
    __syncthreads();
    for (int e = t; e < E_EDGES; e += 1024) {
        int t0 = ei[e];
        int t1 = ei[E_EDGES + e];
        int pos = atomicAdd(&cur[t0], 1);
        g_edge_list[pos] = (t1 << 16) | e;
    }
}

// -------- x preprocess: tf32 round + permute cols within each 16-block --------
// col' = (c%4)*4 + c/4  so one float4 group g holds original cols {g, g+4, g+8, g+12}
__global__ __launch_bounds__(256) void xperm_kernel(const float* __restrict__ x) {
    const int idx = blockIdx.x * 256 + threadIdx.x;   // 0 .. 256*8192-1
    const float v = x[idx];
    uint32_t tv;
    asm("cvt.rna.tf32.f32 %0, %1;" : "=r"(tv) : "f"(v));
    const int col  = idx & 15;
    const int base = idx & ~15;
    g_xperm[base + ((col & 3) << 2) + (col >> 2)] = __uint_as_float(tv);
}

// -------- helpers --------
__device__ __forceinline__ void cp16(uint32_t d, const void* g) {
    asm volatile("cp.async.cg.shared.global [%0], [%1], 16;" :: "r"(d), "l"(g));
}
__device__ __forceinline__ void cp_commit() { asm volatile("cp.async.commit_group;"); }
__device__ __forceinline__ void cp_wait1()  { asm volatile("cp.async.wait_group 1;"); }

__device__ __forceinline__ uint32_t tf32r(float f) {
    uint32_t t;
    asm("cvt.rna.tf32.f32 %0, %1;" : "=r"(t) : "f"(f));
    return t;
}
// D(16x8) += A(16x8 tf32, row) * B(8x8 tf32, col)
__device__ __forceinline__ void mma8(float* c,
                                     uint32_t a0, uint32_t a1, uint32_t a2, uint32_t a3,
                                     uint32_t b0, uint32_t b1) {
    asm volatile(
        "mma.sync.aligned.m16n8k8.row.col.f32.tf32.tf32.f32 "
        "{%0,%1,%2,%3}, {%4,%5,%6,%7}, {%8,%9}, {%0,%1,%2,%3};"
        : "+f"(c[0]), "+f"(c[1]), "+f"(c[2]), "+f"(c[3])
        : "r"(a0), "r"(a1), "r"(a2), "r"(a3), "r"(b0), "r"(b1));
}

union F4U { float4 f; uint32_t u[4]; };

// -------- main tensor SpMM (mma.sync) --------
// grid (512 t0, 2 batch halves), 128 threads = 4 warps; warp w owns batch rows 32w..32w+31.
__global__ __launch_bounds__(128) void spmm_mma(
    const float* __restrict__ values,
    const float* __restrict__ bias,
    float* __restrict__ out)
{
    __shared__ __align__(16) float xs[2][128][16];   // 16 KB: x tiles (permuted cols)
    __shared__ __align__(16) float vt[2][16][16];    //  2 KB: V^T tiles (permuted+swizzled k)

    const int tid  = threadIdx.x;
    const int wid  = tid >> 5;
    const int lane = tid & 31;
    const int gid  = lane >> 2;       // 0..7
    const int tig  = lane & 3;        // 0..3
    const int t0    = blockIdx.x;
    const int bbase = blockIdx.y * BT;

    float acc[2][2][4];
    #pragma unroll
    for (int a = 0; a < 2; a++)
        #pragma unroll
        for (int b = 0; b < 2; b++)
            #pragma unroll
            for (int q = 0; q < 4; q++) acc[a][b][q] = 0.0f;

    // v staging coords: thread handles V elems (i=tid>>3, j=(tid&7)*2) and (i, j+1)
    const int vi = tid >> 3;
    const int vj = (tid & 7) << 1;
    const int kp = ((vi & 3) << 2) + (vi >> 2);             // permuted k position
    const int vcol = kp ^ (((vj >> 1) & 3) << 2);           // XOR swizzle (same for j, j+1)

    // fixed cp.async destinations (thread stages its own batch row)
    uint32_t xdst[2];
    xdst[0] = (uint32_t)__cvta_generic_to_shared(&xs[0][tid][0]);
    xdst[1] = (uint32_t)__cvta_generic_to_shared(&xs[1][tid][0]);

    const int beg = g_offsets[t0];
    const int n   = g_offsets[t0 + 1] - beg;

    if (n > 0) {
        // ---- prologue: stage edge 0 into slot 0 ----
        {
            const int p  = g_edge_list[beg];
            const int e  = p & 0xFFFF;
            const int t1 = p >> 16;
            const float2 vv = __ldg(reinterpret_cast<const float2*>(values + ((size_t)e << 8)) + tid);
            const float* src = g_xperm + (size_t)(bbase + tid) * S1 + t1 * 16;
            #pragma unroll
            for (int ch = 0; ch < 4; ch++) cp16(xdst[0] + ch * 16, src + ch * 4);
            vt[0][vj][vcol]     = __uint_as_float(tf32r(vv.x));
            vt[0][vj + 1][vcol] = __uint_as_float(tf32r(vv.y));
            cp_commit();
        }

        // B-load swizzle column (same key for both N-tiles since (n+8)>>1 ≡ n>>1 mod 4)
        const int bcol = (tig << 2) ^ (((gid >> 1) & 3) << 2);
        const int r0 = (wid << 5) + gid;   // M-tile 0 row
        const int r1 = r0 + 16;            // M-tile 1 row

        for (int k = 0; k < n; k++) {
            const int c = k & 1;

            __syncthreads();   // (A) compute on slot c^1 done -> free to restage

            if (k + 1 < n) {
                const int p  = g_edge_list[beg + k + 1];
                const int e  = p & 0xFFFF;
                const int t1 = p >> 16;
                const float2 vv = __ldg(reinterpret_cast<const float2*>(values + ((size_t)e << 8)) + tid);
                const float* src = g_xperm + (size_t)(bbase + tid) * S1 + t1 * 16;
                #pragma unroll
                for (int ch = 0; ch < 4; ch++) cp16(xdst[c ^ 1] + ch * 16, src + ch * 4);
                vt[c ^ 1][vj][vcol]     = __uint_as_float(tf32r(vv.x));
                vt[c ^ 1][vj + 1][vcol] = __uint_as_float(tf32r(vv.y));
            }
            cp_commit();       // empty commit on last iter keeps group counting aligned
            cp_wait1();        // edge k's x data arrived

            __syncthreads();   // (B) slot c (x async + vt STS from prev iter) visible

            // ---- fragments: 6 LDS.128, conflict-free ----
            F4U aL0, aH0, aL1, aH1, b0, b1;
            aL0.f = *reinterpret_cast<const float4*>(&xs[c][r0    ][tig << 2]);
            aH0.f = *reinterpret_cast<const float4*>(&xs[c][r0 + 8][tig << 2]);
            aL1.f = *reinterpret_cast<const float4*>(&xs[c][r1    ][tig << 2]);
            aH1.f = *reinterpret_cast<const float4*>(&xs[c][r1 + 8][tig << 2]);
            b0.f  = *reinterpret_cast<const float4*>(&vt[c][gid    ][bcol]);
            b1.f  = *reinterpret_cast<const float4*>(&vt[c][gid + 8][bcol]);

            // ---- 8 mma: 2 M-tiles x 2 N-tiles x 2 K-steps ----
            mma8(acc[0][0], aL0.u[0], aH0.u[0], aL0.u[1], aH0.u[1], b0.u[0], b0.u[1]);
            mma8(acc[0][0], aL0.u[2], aH0.u[2], aL0.u[3], aH0.u[3], b0.u[2], b0.u[3]);
            mma8(acc[0][1], aL0.u[0], aH0.u[0], aL0.u[1], aH0.u[1], b1.u[0], b1.u[1]);
            mma8(acc[0][1], aL0.u[2], aH0.u[2], aL0.u[3], aH0.u[3], b1.u[2], b1.u[3]);
            mma8(acc[1][0], aL1.u[0], aH1.u[0], aL1.u[1], aH1.u[1], b0.u[0], b0.u[1]);
            mma8(acc[1][0], aL1.u[2], aH1.u[2], aL1.u[3], aH1.u[3], b0.u[2], b0.u[3]);
            mma8(acc[1][1], aL1.u[0], aH1.u[0], aL1.u[1], aH1.u[1], b1.u[0], b1.u[1]);
            mma8(acc[1][1], aL1.u[2], aH1.u[2], aL1.u[3], aH1.u[3], b1.u[2], b1.u[3]);
        }
    }

    // ---- epilogue: bias + float2 stores (n == 0 -> pure bias) ----
    #pragma unroll
    for (int t = 0; t < 2; t++) {
        const int row = bbase + (wid << 5) + (t << 4) + gid;
        #pragma unroll
        for (int nt = 0; nt < 2; nt++) {
            const int col = t0 * 16 + (nt << 3) + (tig << 1);
            const float2 bv = __ldg(reinterpret_cast<const float2*>(bias + col));
            float2 o0 = make_float2(acc[t][nt][0] + bv.x, acc[t][nt][1] + bv.y);
            float2 o1 = make_float2(acc[t][nt][2] + bv.x, acc[t][nt][3] + bv.y);
            *reinterpret_cast<float2*>(out + (size_t)row * S2 + col)       = o0;
            *reinterpret_cast<float2*>(out + (size_t)(row + 8) * S2 + col) = o1;
        }
    }
}

// -------- launch --------
extern "C" void kernel_launch(void* const* d_in, const int* in_sizes, int n_in,
                              void* d_out, int out_size) {
    const float* x      = (const float*)d_in[0];   // (256, 8192)
    const float* values = (const float*)d_in[1];   // (4194304,)
    const float* bias   = (const float*)d_in[2];   // (8192,)
    const int*   eidx   = (const int*)d_in[3];     // (2, 16384)
    float* out = (float*)d_out;                    // (256, 8192)

    bucket_kernel<<<1, 1024>>>(eidx);
    xperm_kernel<<<(256 * S1) / 256, 256>>>(x);
    dim3 grid(G1, 2);
    spmm_mma<<<grid, 128>>>(values, bias, out);
}